// round 17
// baseline (speedup 1.0000x reference)
#include <cuda_runtime.h>
#include <cuda_bf16.h>
#include <cstdint>

// TangentInvariant — fused, 64 tokens/block, 768 threads (24 warps), 1 CTA/SM.
// K-split x3: 8 steps, each loads 48 KB of B (three 16 KB halves); warp-group
// kg computes chunk 3s+kg. One barrier per step, distance-1 prefetch.
// Phase 1 = proven R11 version. 3-way K-group reduction in epilogue.

#define NT 768

extern __shared__ char smem_raw[];

__device__ __nv_bfloat16 g_kt[128 * 1024];

// ---------------- helpers ----------------
__device__ __forceinline__ unsigned smaddr(const void* p) {
    return (unsigned)__cvta_generic_to_shared(p);
}
__device__ __forceinline__ unsigned sw128(unsigned o) { return o ^ ((o >> 3) & 0x70); }

__device__ __forceinline__ void cp16(unsigned dst, const void* src) {
    asm volatile("cp.async.cg.shared.global [%0], [%1], 16;\n" :: "r"(dst), "l"(src));
}

__device__ __forceinline__ void ldsm_x4(uint32_t& r0, uint32_t& r1,
                                        uint32_t& r2, uint32_t& r3, unsigned a) {
    asm volatile("ldmatrix.sync.aligned.m8n8.x4.shared.b16 {%0,%1,%2,%3}, [%4];"
                 : "=r"(r0), "=r"(r1), "=r"(r2), "=r"(r3) : "r"(a));
}

__device__ __forceinline__ void mma16816(float* c, const uint32_t* a,
                                         uint32_t b0, uint32_t b1) {
    asm volatile(
        "mma.sync.aligned.m16n8k16.row.col.f32.bf16.bf16.f32 "
        "{%0,%1,%2,%3}, {%4,%5,%6,%7}, {%8,%9}, {%0,%1,%2,%3};"
        : "+f"(c[0]), "+f"(c[1]), "+f"(c[2]), "+f"(c[3])
        : "r"(a[0]), "r"(a[1]), "r"(a[2]), "r"(a[3]), "r"(b0), "r"(b1));
}

// ---------------- kernel 1: transpose + split dense_kernel ----------------
__global__ void kprep_kernel(const float* __restrict__ Kd) {
    int idx = blockIdx.x * blockDim.x + threadIdx.x;   // idx = n*1024 + k
    if (idx >= 128 * 1024) return;
    int n = idx >> 10, k = idx & 1023;
    int kk = k & 511;
    float v = (kk < 496) ? Kd[kk * 128 + n] : 0.0f;
    __nv_bfloat16 hi = __float2bfloat16(v);
    if (k < 512) g_kt[idx] = hi;
    else         g_kt[idx] = __float2bfloat16(v - __bfloat162float(hi));
}

// ---------------- fused kernel ----------------
// SMEM (bytes):
//   [0, 131072)          ysm : y split bf16 [64 tok][1024], rows 2048 B,
//                        elem (t,f) at t*2048 + (((f>>3)^(t&7))<<4) + (f&7)*2
//   [131072, 229376)     6 x 16 KB B half-slots (slot = chunk % 6);
//                        during phase 1, [163840, 228480) is phase-1 scratch
//                        (slots 0,1 stay free for the chunk-0/1 prefetch);
//                        in the epilogue slots 0-3 hold the fp32 partials.
static constexpr int YSM_OFF   = 0;
static constexpr int SLOT_OFF  = 131072;
static constexpr int SCR_OFF   = 163840;
static constexpr int SMEM_FUSE = 229376;

// 24 logical chunks:
//   c in [0,8):   A = yh cols c*64          B = Kh cols c*64
//   c in [8,16):  A = yl cols 512+(c-8)*64  B = Kh cols (c-8)*64
//   c in [16,24): A = yh cols (c-16)*64     B = Kl cols 512+(c-16)*64
__device__ __forceinline__ int a_colbase(int c) {
    return (c < 8) ? c * 64 : (c < 16 ? 512 + (c - 8) * 64 : (c - 16) * 64);
}
__device__ __forceinline__ int b_colbase(int c) {
    return (c < 16) ? (c & 7) * 64 : 512 + (c - 16) * 64;
}
__device__ __forceinline__ unsigned slot_addr(unsigned smem_u32, int c) {
    return smem_u32 + SLOT_OFF + (unsigned)(c % 6) * 16384;
}

// load one 16 KB B half (128 rows x 128 B, sw128) for chunk c; no commit
__device__ __forceinline__ void load_half(unsigned smem_u32, int tid, int c) {
    const unsigned dst = slot_addr(smem_u32, c);
    const int bc = b_colbase(c);
    for (int g = tid; g < 1024; g += NT) {
        int row = g >> 3, seg = g & 7;
        unsigned off = sw128((unsigned)(row * 128 + seg * 16));
        cp16(dst + off, g_kt + (size_t)row * 1024 + bc + seg * 8);
    }
}

__global__ __launch_bounds__(NT, 1)
void fused_kernel(const float* __restrict__ x,
                  const float* __restrict__ U0,
                  const float* __restrict__ W0,
                  const float* __restrict__ bias,
                  float* __restrict__ out)
{
    const unsigned smem_u32 = smaddr(smem_raw);
    const unsigned ybase = smem_u32 + YSM_OFF;
    const int tid = threadIdx.x;
    const int wid = tid >> 5;
    const int lid = tid & 31;

    // prefetch chunks 0,1 into slots 0,1 (disjoint from phase-1 scratch)
    load_half(smem_u32, tid, 0);
    load_half(smem_u32, tid, 1);
    asm volatile("cp.async.commit_group;\n" ::: "memory");

    // ================= phase 1 (R11 version) =================
    {
        float* sm  = (float*)(smem_raw + SCR_OFF);
        float* xs  = sm;           // 64*96
        float* vsm = sm + 6144;    // 64*93
        float* wsm = sm + 12096;   // 64*48
        float* Usm = sm + 15168;   // 496
        float* Wsm = sm + 15664;   // 496

        {
            const float4* src = (const float4*)(x + (size_t)blockIdx.x * (64 * 96));
            float4* dst = (float4*)xs;
            for (int g = tid; g < 1536; g += NT) dst[g] = src[g];
            for (int g = tid; g < 496; g += NT) { Usm[g] = U0[g]; Wsm[g] = W0[g]; }
        }
        __syncthreads();

        // sphere log -> v
        for (int idx = tid; idx < 64 * 31; idx += NT) {
            int t = idx / 31;
            int j = idx - t * 31;
            const float* xt = xs + t * 96;
            float px = xt[0], py = xt[1], pz = xt[2];
            const float* q = xt + 3 + j * 3;
            float qx = q[0], qy = q[1], qz = q[2];
            float cs = px * qx + py * qy + pz * qz;
            cs = fminf(1.0f, fmaxf(-1.0f, cs));
            float th = acosf(cs);
            float fac = (th < 1e-6f) ? 1.0f : th / sinf(th);
            float* vo = vsm + t * 93 + j * 3;
            vo[0] = fac * (qx - cs * px);
            vo[1] = fac * (qy - cs * py);
            vo[2] = fac * (qz - cs * pz);
        }
        __syncthreads();

        // VN layer -> w
        for (int idx = tid; idx < 64 * 16; idx += NT) {
            int t = idx >> 4;
            int i = idx & 15;
            const float* vb = vsm + t * 93;
            const float* Ur = Usm + i * 31;
            const float* Wr = Wsm + i * 31;
            float kx = 0.f, ky = 0.f, kz = 0.f, qx = 0.f, qy = 0.f, qz = 0.f;
            #pragma unroll
            for (int j = 0; j < 31; ++j) {
                float u = Ur[j], w_ = Wr[j];
                float vx = vb[j * 3 + 0], vy = vb[j * 3 + 1], vz = vb[j * 3 + 2];
                kx += u * vx;  ky += u * vy;  kz += u * vz;
                qx += w_ * vx; qy += w_ * vy; qz += w_ * vz;
            }
            float sq = kx * kx + ky * ky + kz * kz + 2.2204460492503131e-16f;
            float dt = qx * kx + qy * ky + qz * kz;
            float r = 0.8f * fmaxf(-dt, 0.0f) / sq;
            float* wo = wsm + t * 48 + i * 3;
            wo[0] = qx + r * kx;
            wo[1] = qy + r * ky;
            wo[2] = qz + r * kz;
        }
        __syncthreads();

        // Gram -> split bf16 into ysm
        for (int idx = tid; idx < 64 * 256; idx += NT) {
            int t = idx >> 8;
            int fp = (idx & 255) * 2;
            float y0 = 0.0f, y1 = 0.0f;
            if (fp < 496) {
                const float* vv = vsm + t * 93 + (fp >> 4) * 3;
                const float* w0 = wsm + t * 48 + (fp & 15) * 3;
                y0 = vv[0] * w0[0] + vv[1] * w0[1] + vv[2] * w0[2];
                int f1 = fp + 1;
                const float* vv1 = vsm + t * 93 + (f1 >> 4) * 3;
                const float* w1 = wsm + t * 48 + (f1 & 15) * 3;
                y1 = vv1[0] * w1[0] + vv1[1] * w1[1] + vv1[2] * w1[2];
            }
            __nv_bfloat16 h0 = __float2bfloat16(y0);
            __nv_bfloat16 h1 = __float2bfloat16(y1);
            __nv_bfloat16 l0 = __float2bfloat16(y0 - __bfloat162float(h0));
            __nv_bfloat16 l1 = __float2bfloat16(y1 - __bfloat162float(h1));
            const int x7 = t & 7;
            unsigned ga = (unsigned)((fp >> 3) ^ x7);
            unsigned ah = ybase + (unsigned)t * 2048 + (ga << 4) + (unsigned)(fp & 7) * 2;
            unsigned gb = (unsigned)(((512 + fp) >> 3) ^ x7);
            unsigned al = ybase + (unsigned)t * 2048 + (gb << 4) + (unsigned)(fp & 7) * 2;
            unsigned hv = ((unsigned)*(uint16_t*)&h1 << 16) | *(uint16_t*)&h0;
            unsigned lv = ((unsigned)*(uint16_t*)&l1 << 16) | *(uint16_t*)&l0;
            asm volatile("st.shared.b32 [%0], %1;" :: "r"(ah), "r"(hv) : "memory");
            asm volatile("st.shared.b32 [%0], %1;" :: "r"(al), "r"(lv) : "memory");
        }
    }
    __syncthreads();   // phase-1 scratch dead; slots 2..5 free

    // finish step 0 (chunk 2) and load step 1 (chunks 3,4,5)
    load_half(smem_u32, tid, 2);
    asm volatile("cp.async.commit_group;\n" ::: "memory");
    load_half(smem_u32, tid, 3);
    load_half(smem_u32, tid, 4);
    load_half(smem_u32, tid, 5);
    asm volatile("cp.async.commit_group;\n" ::: "memory");

    // ================= phase 2: GEMM 64x128x1536, K-split x3 =================
    // warp layout: kg = wid>>3 (0..2), m_w = (wid>>2)&1, n_w = wid&3
    // warp tile 32(M) x 32(N); step s: warp computes chunk 3s+kg.
    const int kg     = wid >> 3;
    const int m_base = ((wid >> 2) & 1) * 32;
    const int n_base = (wid & 3) * 32;

    const int a_r  = m_base + ((lid >> 3) & 1) * 8 + (lid & 7);
    const int a_c8 = (lid >> 4) & 1;
    const int ax7  = a_r & 7;
    const unsigned a_rowaddr = ybase + (unsigned)a_r * 2048;

    const int b_r  = ((lid >> 4) & 1) * 8 + (lid & 7);
    const unsigned b_cb = (unsigned)(((lid >> 3) & 1) * 16);

    float acc[2][4][4];   // [mt][nt][frag]
    #pragma unroll
    for (int i = 0; i < 2; ++i)
        #pragma unroll
        for (int j = 0; j < 4; ++j)
            #pragma unroll
            for (int k = 0; k < 4; ++k) acc[i][j][k] = 0.0f;

    for (int s = 0; s < 8; ++s) {
        // barrier: all warps done with step s-1 -> its slots (= step s+1's) free
        __syncthreads();
        // prefetch step s+1 (distance 1; hides under this step's compute)
        if (s + 1 < 8) {
            load_half(smem_u32, tid, 3 * s + 3);
            load_half(smem_u32, tid, 3 * s + 4);
            load_half(smem_u32, tid, 3 * s + 5);
        }
        asm volatile("cp.async.commit_group;\n" ::: "memory");
        // wait for step s's halves (allow step s+1's group outstanding)
        asm volatile("cp.async.wait_group 1;\n" ::: "memory");

        const int c = 3 * s + kg;
        const unsigned bchunk = slot_addr(smem_u32, c);
        const int acol = a_colbase(c);

        #pragma unroll
        for (int ks = 0; ks < 4; ++ks) {
            uint32_t a[2][4];
            {
                int agrp = (acol >> 3) + ks * 2 + a_c8;
                unsigned g = (unsigned)(agrp ^ ax7);
                unsigned ad0 = a_rowaddr + (g << 4);
                ldsm_x4(a[0][0], a[0][1], a[0][2], a[0][3], ad0);
                ldsm_x4(a[1][0], a[1][1], a[1][2], a[1][3], ad0 + 16 * 2048);
            }
            #pragma unroll
            for (int ntp = 0; ntp < 2; ++ntp) {
                unsigned off = (unsigned)((n_base + ntp * 16 + b_r) * 128)
                             + (unsigned)(ks * 32) + b_cb;
                uint32_t r0, r1, r2, r3;
                ldsm_x4(r0, r1, r2, r3, bchunk + sw128(off));
                #pragma unroll
                for (int mt = 0; mt < 2; ++mt) {
                    mma16816(acc[mt][ntp * 2 + 0], a[mt], r0, r1);
                    mma16816(acc[mt][ntp * 2 + 1], a[mt], r2, r3);
                }
            }
        }
    }

    // ---- epilogue: 3-way K-group reduction through smem, bias, store ----
    __syncthreads();   // all slots dead
    float* red1 = (float*)(smem_raw + SLOT_OFF);            // kg1 partial, 32 KB
    float* red2 = (float*)(smem_raw + SLOT_OFF + 32768);    // kg2 partial, 32 KB
    const int gr = lid >> 2;
    const int gc = (lid & 3) * 2;

    if (kg > 0) {
        float* red = (kg == 1) ? red1 : red2;
        #pragma unroll
        for (int mt = 0; mt < 2; ++mt)
            #pragma unroll
            for (int nt = 0; nt < 4; ++nt) {
                const int r0 = m_base + mt * 16 + gr;
                const int n_ = n_base + nt * 8 + gc;
                *(float2*)(red + r0 * 128 + n_)       = make_float2(acc[mt][nt][0], acc[mt][nt][1]);
                *(float2*)(red + (r0 + 8) * 128 + n_) = make_float2(acc[mt][nt][2], acc[mt][nt][3]);
            }
    }
    __syncthreads();

    if (kg == 0) {
        const size_t m0 = (size_t)blockIdx.x * 64;
        #pragma unroll
        for (int nt = 0; nt < 4; ++nt) {
            const int n_ = n_base + nt * 8 + gc;
            const float b0 = bias[n_], b1 = bias[n_ + 1];
            #pragma unroll
            for (int mt = 0; mt < 2; ++mt) {
                const int r0 = m_base + mt * 16 + gr;
                float2 p0 = *(const float2*)(red1 + r0 * 128 + n_);
                float2 q0 = *(const float2*)(red2 + r0 * 128 + n_);
                float2 p1 = *(const float2*)(red1 + (r0 + 8) * 128 + n_);
                float2 q1 = *(const float2*)(red2 + (r0 + 8) * 128 + n_);
                float2 o0, o1;
                o0.x = acc[mt][nt][0] + p0.x + q0.x + b0;
                o0.y = acc[mt][nt][1] + p0.y + q0.y + b1;
                o1.x = acc[mt][nt][2] + p1.x + q1.x + b0;
                o1.y = acc[mt][nt][3] + p1.y + q1.y + b1;
                *(float2*)(out + (m0 + r0) * 128 + n_)     = o0;
                *(float2*)(out + (m0 + r0 + 8) * 128 + n_) = o1;
            }
        }
    }
}

// ---------------- launch ----------------
extern "C" void kernel_launch(void* const* d_in, const int* in_sizes, int n_in,
                              void* d_out, int out_size) {
    const float* x    = (const float*)d_in[0];
    const float* U0   = (const float*)d_in[1];
    const float* W0   = (const float*)d_in[2];
    const float* Kd   = (const float*)d_in[3];
    const float* bias = (const float*)d_in[4];
    float* o = (float*)d_out;

    cudaFuncSetAttribute(fused_kernel,
                         cudaFuncAttributeMaxDynamicSharedMemorySize, SMEM_FUSE);

    kprep_kernel<<<512, 256>>>(Kd);
    fused_kernel<<<2048, NT, SMEM_FUSE>>>(x, U0, W0, bias, o);
}